// round 17
// baseline (speedup 1.0000x reference)
#include <cuda_runtime.h>

// preds: [16,8,17,128,128] f32 -> N=128, K=17, H=W=128
// gt:    [16,8,10,17,2]    f32 -> [N=128, P=10, K=17, 2]
// out:   2 floats (total_within, total_across)
#define N_TOT 128
#define P_NUM 10
#define K_NUM 17
#define HH 128
#define WW 128
#define INV_STRIDE 0.25f
#define NTH 1024
#define NWORK (N_TOT * P_NUM * K_NUM)          // 21760
#define SMEM_BYTES ((2 * NWORK + 64) * 4)      // val + msk + 64 reduction slots

__global__ void __launch_bounds__(NTH, 1)
group_loss_single(const float* __restrict__ preds,
                  const float* __restrict__ gt,
                  float* __restrict__ out) {
    extern __shared__ float sm[];
    float* s_val = sm;                 // [NWORK]
    float* s_msk = sm + NWORK;         // [NWORK]
    float* s_red = sm + 2 * NWORK;     // [64]: W partials [0..31], A partials [32..63]

    const int t = threadIdx.x;

    // ---- Phase A: gather all 21760 scattered values into smem ----
    // idx = (n*10+p)*17 + k  (same linear order as gt)
#pragma unroll 4
    for (int idx = t; idx < NWORK; idx += NTH) {
        const float2 g = __ldg((const float2*)gt + idx);
        const int np = idx / K_NUM;          // n*10+p
        const int k  = idx - np * K_NUM;
        const int n  = np / P_NUM;
        const int x = (int)rintf(g.x * INV_STRIDE);  // jnp.round = round-half-even
        const int y = (int)rintf(g.y * INV_STRIDE);
        const bool valid = (x >= 0) && (x < WW) && (y >= 0) && (y < HH);
        const int xc = min(max(x, 0), WW - 1);
        const int yc = min(max(y, 0), HH - 1);
        const float v = __ldg(&preds[((n * K_NUM + k) * HH + yc) * WW + xc]);
        s_val[idx] = valid ? v : 0.0f;
        s_msk[idx] = valid ? 1.0f : 0.0f;
    }
    __syncthreads();

    // ---- Phase B: 32 warps, warp w handles n = w, w+32, w+64, w+96 ----
    const int w    = t >> 5;
    const int lane = t & 31;
    float accW = 0.0f, accA = 0.0f;

    for (int n = w; n < N_TOT; n += 32) {
        // lanes 0..9: per-person moments (single pass)
        float e = 0.0f, pv = 0.0f, wp = 0.0f;
        if (lane < P_NUM) {
            const int base = (n * P_NUM + lane) * K_NUM;
            float sum = 0.0f, sumsq = 0.0f, cnt = 0.0f;
#pragma unroll
            for (int k = 0; k < K_NUM; k++) {
                const float v = s_val[base + k];
                sum   += v;
                sumsq += v * v;               // masked entries already 0
                cnt   += s_msk[base + k];
            }
            const float safe = fmaxf(cnt, 1.0f);
            e = sum / safe;
            wp = (sumsq - 2.0f * e * sum + e * e * cnt) / safe;
            if (!(cnt > 0.0f)) wp = 0.0f;
            pv = (cnt > 0.0f) ? 1.0f : 0.0f;
        }

        // pairwise hinge: broadcast each person's (e, pv) via shfl
        float hs = 0.0f, dn = 0.0f;
#pragma unroll
        for (int j = 0; j < P_NUM; j++) {
            const float ej  = __shfl_sync(0xFFFFFFFFu, e,  j);
            const float pvj = __shfl_sync(0xFFFFFFFFu, pv, j);
            if (lane < P_NUM && j != lane) {
                const float pair = pv * pvj;
                hs += fmaxf(1.0f - fabsf(ej - e), 0.0f) * pair;
                dn += pair;
            }
        }

        // reduce wp/hs/dn over lanes 0..9 (start at offset 8)
#pragma unroll
        for (int o = 8; o > 0; o >>= 1) {
            wp += __shfl_down_sync(0xFFFFFFFFu, wp, o);
            hs += __shfl_down_sync(0xFFFFFFFFu, hs, o);
            dn += __shfl_down_sync(0xFFFFFFFFu, dn, o);
        }
        if (lane == 0) {
            accW += wp * (1.0f / (float)P_NUM);
            accA += (dn > 0.0f) ? (hs / fmaxf(dn, 1.0f)) : 0.0f;
        }
    }

    if (lane == 0) {
        s_red[w]      = accW;
        s_red[32 + w] = accA;
    }
    __syncthreads();

    // ---- Phase C: warp 0 reduces 32 partials, writes output ----
    if (t < 32) {
        float W = s_red[t];
        float A = s_red[32 + t];
#pragma unroll
        for (int o = 16; o > 0; o >>= 1) {
            W += __shfl_down_sync(0xFFFFFFFFu, W, o);
            A += __shfl_down_sync(0xFFFFFFFFu, A, o);
        }
        if (t == 0) {
            out[0] = W * (1.0f / (float)N_TOT);
            out[1] = A * (1.0f / (float)N_TOT);
        }
    }
}

extern "C" void kernel_launch(void* const* d_in, const int* in_sizes, int n_in,
                              void* d_out, int out_size) {
    const float* preds = (const float*)d_in[0];
    const float* gt    = (const float*)d_in[1];
    float* out = (float*)d_out;
    // idempotent; needed for >48KB dynamic smem (174KB used)
    cudaFuncSetAttribute(group_loss_single,
                         cudaFuncAttributeMaxDynamicSharedMemorySize, SMEM_BYTES);
    group_loss_single<<<1, NTH, SMEM_BYTES>>>(preds, gt, out);
}